// round 2
// baseline (speedup 1.0000x reference)
#include <cuda_runtime.h>
#include <cuda_bf16.h>

// Problem sizes (fixed by setup_inputs)
#define BSZ 4
#define HH  64
#define WW  64
#define CC  256
#define DD  128
#define NN  4096          // HH*WW
#define MM  4095          // NN-1 (maxpool 2, stride 1, valid)

// Scratch (device globals are the sanctioned scratch mechanism)
__device__ __align__(16) float g_theta[BSZ*NN*DD];
__device__ __align__(16) float g_phi  [BSZ*NN*DD];
__device__ __align__(16) float g_gv   [BSZ*NN*DD];
__device__ __align__(16) float g_phip [BSZ*NN*DD];   // pooled keys (row NN-1 unused)
__device__ __align__(16) float g_gp   [BSZ*NN*DD];   // pooled values
__device__ __align__(16) float g_y    [BSZ*NN*DD];   // attention output

// ---------------------------------------------------------------------------
// Kernel 1: projections  out = x @ W   ([16384,256] @ [256,128])
// grid (256 row-tiles, 3 weights), 256 threads, 64x128 tile, K-chunks of 32
// ---------------------------------------------------------------------------
__global__ void proj_kernel(const float* __restrict__ x,
                            const float* __restrict__ W0,
                            const float* __restrict__ W1,
                            const float* __restrict__ W2)
{
    __shared__ __align__(16) float As[64][32];
    __shared__ __align__(16) float Bs[32][128];

    const float* Wm = (blockIdx.y == 0) ? W0 : (blockIdx.y == 1) ? W1 : W2;
    float* out = (blockIdx.y == 0) ? g_theta : (blockIdx.y == 1) ? g_phi : g_gv;

    const int tid = threadIdx.x;
    const int ty = tid >> 4;       // 0..15
    const int tx = tid & 15;       // 0..15
    const int row0 = blockIdx.x * 64;

    float acc[4][8];
#pragma unroll
    for (int i = 0; i < 4; i++)
#pragma unroll
        for (int j = 0; j < 8; j++) acc[i][j] = 0.f;

    for (int kc = 0; kc < CC; kc += 32) {
        // load A tile: 64x32 = 512 float4, 2 per thread
#pragma unroll
        for (int p = 0; p < 2; p++) {
            int idx = tid + p * 256;
            int r = idx >> 3;             // /8 float4 per row
            int c = (idx & 7) << 2;
            float4 v = *(const float4*)&x[(size_t)(row0 + r) * CC + kc + c];
            *(float4*)&As[r][c] = v;
        }
        // load B tile: 32x128 = 1024 float4, 4 per thread
#pragma unroll
        for (int p = 0; p < 4; p++) {
            int idx = tid + p * 256;
            int r = idx >> 5;             // /32 float4 per row
            int c = (idx & 31) << 2;
            float4 v = *(const float4*)&Wm[(size_t)(kc + r) * DD + c];
            *(float4*)&Bs[r][c] = v;
        }
        __syncthreads();

#pragma unroll
        for (int k = 0; k < 32; k++) {
            float a[4];
#pragma unroll
            for (int i = 0; i < 4; i++) a[i] = As[ty * 4 + i][k];
            float4 b0 = *(float4*)&Bs[k][tx * 8];
            float4 b1 = *(float4*)&Bs[k][tx * 8 + 4];
            float b[8] = {b0.x, b0.y, b0.z, b0.w, b1.x, b1.y, b1.z, b1.w};
#pragma unroll
            for (int i = 0; i < 4; i++)
#pragma unroll
                for (int j = 0; j < 8; j++) acc[i][j] = fmaf(a[i], b[j], acc[i][j]);
        }
        __syncthreads();
    }

#pragma unroll
    for (int i = 0; i < 4; i++) {
        float4 o0 = {acc[i][0], acc[i][1], acc[i][2], acc[i][3]};
        float4 o1 = {acc[i][4], acc[i][5], acc[i][6], acc[i][7]};
        size_t base = (size_t)(row0 + ty * 4 + i) * DD + tx * 8;
        *(float4*)&out[base]     = o0;
        *(float4*)&out[base + 4] = o1;
    }
}

// ---------------------------------------------------------------------------
// Kernel 2: maxpool over sequence (pool 2, stride 1, valid)
// ---------------------------------------------------------------------------
__global__ void pool_kernel()
{
    int i = blockIdx.x * blockDim.x + threadIdx.x;   // over BSZ*NN*DD
    if (i >= BSZ * NN * DD) return;
    int r = i % (NN * DD);
    int m = r / DD;
    if (m < NN - 1) {
        g_phip[i] = fmaxf(g_phi[i], g_phi[i + DD]);
        g_gp[i]   = fmaxf(g_gv[i],  g_gv[i + DD]);
    }
}

// ---------------------------------------------------------------------------
// Kernel 3: fused flash attention (no scale, softmax over M keys)
// grid (64 query-tiles, 4 batches), 256 threads, 64 queries x D=128 per block
// dyn smem: Q 64x128 | K 64x128 | V 64x128 | P 64x64  = 112 KB
// ---------------------------------------------------------------------------
__global__ void attn_kernel()
{
    extern __shared__ __align__(16) float sm[];
    float* Qs = sm;                 // 8192
    float* Ks = Qs + 64 * DD;       // 8192
    float* Vs = Ks + 64 * DD;       // 8192
    float* Ps = Vs + 64 * DD;       // 4096

    const int b  = blockIdx.y;
    const int q0 = blockIdx.x * 64;
    const float* Qg = g_theta + (size_t)b * NN * DD;
    const float* Kg = g_phip  + (size_t)b * NN * DD;
    const float* Vg = g_gp    + (size_t)b * NN * DD;

    const int tid = threadIdx.x;
    const int ty = tid >> 4;        // 0..15 -> rows ty*4..ty*4+3
    const int tx = tid & 15;        // 0..15

    // load Q tile: 2048 float4, 8 per thread
    {
        const float4* src = (const float4*)(Qg + (size_t)q0 * DD);
        float4* dst = (float4*)Qs;
#pragma unroll
        for (int p = 0; p < 8; p++) dst[tid + p * 256] = src[tid + p * 256];
    }

    float O[4][8];
    float mrow[4], lrow[4];
#pragma unroll
    for (int i = 0; i < 4; i++) {
        mrow[i] = -1e30f; lrow[i] = 0.f;
#pragma unroll
        for (int j = 0; j < 8; j++) O[i][j] = 0.f;
    }
    __syncthreads();

    for (int kt = 0; kt < 64; kt++) {
        // load K,V tiles (prev iteration consumers done via loop-end sync)
        {
            const float4* ks = (const float4*)(Kg + (size_t)kt * 64 * DD);
            const float4* vs = (const float4*)(Vg + (size_t)kt * 64 * DD);
            float4* kd = (float4*)Ks;
            float4* vd = (float4*)Vs;
#pragma unroll
            for (int p = 0; p < 8; p++) {
                kd[tid + p * 256] = ks[tid + p * 256];
                vd[tid + p * 256] = vs[tid + p * 256];
            }
        }
        __syncthreads();

        // S = Q @ K^T  (4x4 microtile per thread)
        float S[4][4];
#pragma unroll
        for (int i = 0; i < 4; i++)
#pragma unroll
            for (int j = 0; j < 4; j++) S[i][j] = 0.f;

#pragma unroll 4
        for (int k = 0; k < DD; k += 4) {
            float4 a[4], bb[4];
#pragma unroll
            for (int i = 0; i < 4; i++) a[i]  = *(float4*)&Qs[(ty * 4 + i) * DD + k];
#pragma unroll
            for (int j = 0; j < 4; j++) bb[j] = *(float4*)&Ks[(tx * 4 + j) * DD + k];
#pragma unroll
            for (int i = 0; i < 4; i++)
#pragma unroll
                for (int j = 0; j < 4; j++) {
                    S[i][j] = fmaf(a[i].x, bb[j].x, S[i][j]);
                    S[i][j] = fmaf(a[i].y, bb[j].y, S[i][j]);
                    S[i][j] = fmaf(a[i].z, bb[j].z, S[i][j]);
                    S[i][j] = fmaf(a[i].w, bb[j].w, S[i][j]);
                }
        }

        // mask invalid keys (only last key of last tile: m = 4095)
        if (kt == 63) {
#pragma unroll
            for (int j = 0; j < 4; j++)
                if (kt * 64 + tx * 4 + j >= MM)
#pragma unroll
                    for (int i = 0; i < 4; i++) S[i][j] = -1e30f;
        }

        // row max across the 16 tx threads (lanes within half-warp)
        float mloc[4];
#pragma unroll
        for (int i = 0; i < 4; i++) {
            mloc[i] = fmaxf(fmaxf(S[i][0], S[i][1]), fmaxf(S[i][2], S[i][3]));
        }
#pragma unroll
        for (int off = 8; off >= 1; off >>= 1)
#pragma unroll
            for (int i = 0; i < 4; i++)
                mloc[i] = fmaxf(mloc[i], __shfl_xor_sync(0xffffffffu, mloc[i], off));

        float scale[4], psum[4];
#pragma unroll
        for (int i = 0; i < 4; i++) {
            float mnew = fmaxf(mrow[i], mloc[i]);
            scale[i] = __expf(mrow[i] - mnew);
            mrow[i] = mnew;
            float p0 = __expf(S[i][0] - mnew);
            float p1 = __expf(S[i][1] - mnew);
            float p2 = __expf(S[i][2] - mnew);
            float p3 = __expf(S[i][3] - mnew);
            float4 pv = {p0, p1, p2, p3};
            *(float4*)&Ps[(ty * 4 + i) * 64 + tx * 4] = pv;
            psum[i] = (p0 + p1) + (p2 + p3);
        }
#pragma unroll
        for (int off = 8; off >= 1; off >>= 1)
#pragma unroll
            for (int i = 0; i < 4; i++)
                psum[i] += __shfl_xor_sync(0xffffffffu, psum[i], off);
#pragma unroll
        for (int i = 0; i < 4; i++) {
            lrow[i] = lrow[i] * scale[i] + psum[i];
#pragma unroll
            for (int j = 0; j < 8; j++) O[i][j] *= scale[i];
        }
        __syncthreads();

        // O += P @ V   (rows ty*4+i, cols tx*8+j)
#pragma unroll 4
        for (int k = 0; k < 64; k++) {
            float a[4];
#pragma unroll
            for (int i = 0; i < 4; i++) a[i] = Ps[(ty * 4 + i) * 64 + k];
            float4 v0 = *(float4*)&Vs[k * DD + tx * 8];
            float4 v1 = *(float4*)&Vs[k * DD + tx * 8 + 4];
            float v[8] = {v0.x, v0.y, v0.z, v0.w, v1.x, v1.y, v1.z, v1.w};
#pragma unroll
            for (int i = 0; i < 4; i++)
#pragma unroll
                for (int j = 0; j < 8; j++) O[i][j] = fmaf(a[i], v[j], O[i][j]);
        }
        __syncthreads();
    }

    // epilogue: normalize and store y
    float* yout = g_y + (size_t)b * NN * DD;
#pragma unroll
    for (int i = 0; i < 4; i++) {
        float inv = 1.f / lrow[i];
        float4 o0 = {O[i][0] * inv, O[i][1] * inv, O[i][2] * inv, O[i][3] * inv};
        float4 o1 = {O[i][4] * inv, O[i][5] * inv, O[i][6] * inv, O[i][7] * inv};
        size_t base = (size_t)(q0 + ty * 4 + i) * DD + tx * 8;
        *(float4*)&yout[base]     = o0;
        *(float4*)&yout[base + 4] = o1;
    }
}

// ---------------------------------------------------------------------------
// Kernel 4: z = x + y @ Wf   ([16384,128] @ [128,256])
// grid (256 row-tiles, 4 col-tiles of 64), 256 threads
// ---------------------------------------------------------------------------
__global__ void out_kernel(const float* __restrict__ x,
                           const float* __restrict__ Wf,
                           float* __restrict__ z)
{
    __shared__ __align__(16) float Ys[64][DD];   // 32 KB

    const int tid = threadIdx.x;
    const int ty = tid >> 4;
    const int tx = tid & 15;
    const int row0 = blockIdx.x * 64;
    const int c0 = blockIdx.y * 64;

    // load Y tile: 2048 float4, 8 per thread
    {
        const float4* src = (const float4*)(g_y + (size_t)row0 * DD);
        float4* dst = (float4*)&Ys[0][0];
#pragma unroll
        for (int p = 0; p < 8; p++) dst[tid + p * 256] = src[tid + p * 256];
    }
    __syncthreads();

    float acc[4][4];
#pragma unroll
    for (int i = 0; i < 4; i++)
#pragma unroll
        for (int j = 0; j < 4; j++) acc[i][j] = 0.f;

    const float4* Wf4 = (const float4*)Wf;   // row k: 64 float4
#pragma unroll 4
    for (int k = 0; k < DD; k++) {
        float a[4];
#pragma unroll
        for (int i = 0; i < 4; i++) a[i] = Ys[ty * 4 + i][k];
        float4 w = __ldg(&Wf4[(size_t)k * (CC / 4) + (c0 >> 2) + tx]);
#pragma unroll
        for (int i = 0; i < 4; i++) {
            acc[i][0] = fmaf(a[i], w.x, acc[i][0]);
            acc[i][1] = fmaf(a[i], w.y, acc[i][1]);
            acc[i][2] = fmaf(a[i], w.z, acc[i][2]);
            acc[i][3] = fmaf(a[i], w.w, acc[i][3]);
        }
    }

#pragma unroll
    for (int i = 0; i < 4; i++) {
        size_t base = (size_t)(row0 + ty * 4 + i) * CC + c0 + tx * 4;
        float4 xv = *(const float4*)&x[base];
        float4 o = {xv.x + acc[i][0], xv.y + acc[i][1],
                    xv.z + acc[i][2], xv.w + acc[i][3]};
        *(float4*)&z[base] = o;
    }
}

// ---------------------------------------------------------------------------
extern "C" void kernel_launch(void* const* d_in, const int* in_sizes, int n_in,
                              void* d_out, int out_size)
{
    const float* x  = (const float*)d_in[0];
    const float* Wt = (const float*)d_in[1];
    const float* Wp = (const float*)d_in[2];
    const float* Wg = (const float*)d_in[3];
    const float* Wf = (const float*)d_in[4];
    float* z = (float*)d_out;

    const int ATTN_SMEM = (64 * DD * 3 + 64 * 64) * sizeof(float);  // 114688
    cudaFuncSetAttribute(attn_kernel, cudaFuncAttributeMaxDynamicSharedMemorySize,
                         ATTN_SMEM);

    proj_kernel<<<dim3(BSZ * NN / 64, 3), 256>>>(x, Wt, Wp, Wg);
    pool_kernel<<<(BSZ * NN * DD) / 256, 256>>>();
    attn_kernel<<<dim3(NN / 64, BSZ), 256, ATTN_SMEM>>>();
    out_kernel<<<dim3(BSZ * NN / 64, CC / 64), 256>>>(x, Wf, z);
}

// round 6
// speedup vs baseline: 6.2161x; 6.2161x over previous
#include <cuda_runtime.h>
#include <cuda_bf16.h>
#include <cstdint>

#define BSZ 4
#define CC  256
#define DD  128
#define NN  4096
#define MM  4095
#define NKT 64              // key tiles of 64

// ---------------- scratch ----------------
__device__ __align__(16) __nv_bfloat16 g_th[BSZ*NN*DD];
__device__ __align__(16) __nv_bfloat16 g_tl[BSZ*NN*DD];
__device__ __align__(16) float g_phi[BSZ*NN*DD];
__device__ __align__(16) float g_gv [BSZ*NN*DD];
__device__ __align__(16) __nv_bfloat16 g_kh[BSZ*NN*DD];
__device__ __align__(16) __nv_bfloat16 g_kl[BSZ*NN*DD];
__device__ __align__(16) __nv_bfloat16 g_vh[BSZ*NN*DD];
__device__ __align__(16) __nv_bfloat16 g_vl[BSZ*NN*DD];
__device__ __align__(16) float g_y[BSZ*NN*DD];

// ---------------- helpers ----------------
__device__ __forceinline__ uint32_t s2u(const void* p){
    uint32_t a;
    asm("{ .reg .u64 t; cvta.to.shared.u64 t, %1; cvt.u32.u64 %0, t; }" : "=r"(a) : "l"(p));
    return a;
}
__device__ __forceinline__ void ldsm_x4(uint32_t* r, uint32_t a){
    asm volatile("ldmatrix.sync.aligned.m8n8.x4.shared.b16 {%0,%1,%2,%3}, [%4];"
        : "=r"(r[0]),"=r"(r[1]),"=r"(r[2]),"=r"(r[3]) : "r"(a));
}
__device__ __forceinline__ void ldsm_x2(uint32_t* r, uint32_t a){
    asm volatile("ldmatrix.sync.aligned.m8n8.x2.shared.b16 {%0,%1}, [%2];"
        : "=r"(r[0]),"=r"(r[1]) : "r"(a));
}
__device__ __forceinline__ void ldsm_x4t(uint32_t* r, uint32_t a){
    asm volatile("ldmatrix.sync.aligned.m8n8.x4.trans.shared.b16 {%0,%1,%2,%3}, [%4];"
        : "=r"(r[0]),"=r"(r[1]),"=r"(r[2]),"=r"(r[3]) : "r"(a));
}
__device__ __forceinline__ void mma16816(float* c, const uint32_t* a, const uint32_t* b){
    asm volatile("mma.sync.aligned.m16n8k16.row.col.f32.bf16.bf16.f32 "
        "{%0,%1,%2,%3}, {%4,%5,%6,%7}, {%8,%9}, {%0,%1,%2,%3};"
        : "+f"(c[0]),"+f"(c[1]),"+f"(c[2]),"+f"(c[3])
        : "r"(a[0]),"r"(a[1]),"r"(a[2]),"r"(a[3]),"r"(b[0]),"r"(b[1]));
}
__device__ __forceinline__ uint32_t packbf(float lo, float hi){
    uint32_t r; asm("cvt.rn.bf16x2.f32 %0, %1, %2;" : "=r"(r) : "f"(hi), "f"(lo)); return r;
}
__device__ __forceinline__ __nv_bfloat16 bhi(float v){ return __float2bfloat16(v); }
__device__ __forceinline__ __nv_bfloat16 blo(float v, __nv_bfloat16 h){
    return __float2bfloat16(v - __bfloat162float(h));
}

// ---------------- kernel 1: projections ----------------
__global__ void proj_kernel(const float* __restrict__ x,
                            const float* __restrict__ W0,
                            const float* __restrict__ W1,
                            const float* __restrict__ W2)
{
    __shared__ __align__(16) float As[64][32];
    __shared__ __align__(16) float Bs[32][128];
    const float* Wm = (blockIdx.y == 0) ? W0 : (blockIdx.y == 1) ? W1 : W2;
    const int tid = threadIdx.x, ty = tid >> 4, tx = tid & 15;
    const int row0 = blockIdx.x * 64;

    float acc[4][8];
#pragma unroll
    for (int i = 0; i < 4; i++)
#pragma unroll
        for (int j = 0; j < 8; j++) acc[i][j] = 0.f;

    for (int kc = 0; kc < CC; kc += 32) {
#pragma unroll
        for (int p = 0; p < 2; p++) {
            int idx = tid + p * 256, r = idx >> 3, c = (idx & 7) << 2;
            *(float4*)&As[r][c] = *(const float4*)&x[(size_t)(row0 + r) * CC + kc + c];
        }
#pragma unroll
        for (int p = 0; p < 4; p++) {
            int idx = tid + p * 256, r = idx >> 5, c = (idx & 31) << 2;
            *(float4*)&Bs[r][c] = *(const float4*)&Wm[(size_t)(kc + r) * DD + c];
        }
        __syncthreads();
#pragma unroll
        for (int k = 0; k < 32; k++) {
            float a[4];
#pragma unroll
            for (int i = 0; i < 4; i++) a[i] = As[ty * 4 + i][k];
            float4 b0 = *(float4*)&Bs[k][tx * 8];
            float4 b1 = *(float4*)&Bs[k][tx * 8 + 4];
            float b[8] = {b0.x, b0.y, b0.z, b0.w, b1.x, b1.y, b1.z, b1.w};
#pragma unroll
            for (int i = 0; i < 4; i++)
#pragma unroll
                for (int j = 0; j < 8; j++) acc[i][j] = fmaf(a[i], b[j], acc[i][j]);
        }
        __syncthreads();
    }

    if (blockIdx.y == 0) {
#pragma unroll
        for (int i = 0; i < 4; i++) {
            size_t base = (size_t)(row0 + ty * 4 + i) * DD + tx * 8;
#pragma unroll
            for (int j = 0; j < 8; j += 2) {
                __nv_bfloat16 h0 = bhi(acc[i][j]),   h1 = bhi(acc[i][j+1]);
                __nv_bfloat162 ph; ph.x = h0; ph.y = h1;
                __nv_bfloat162 pl; pl.x = blo(acc[i][j], h0); pl.y = blo(acc[i][j+1], h1);
                *(__nv_bfloat162*)(g_th + base + j) = ph;
                *(__nv_bfloat162*)(g_tl + base + j) = pl;
            }
        }
    } else {
        float* out = (blockIdx.y == 1) ? g_phi : g_gv;
#pragma unroll
        for (int i = 0; i < 4; i++) {
            size_t base = (size_t)(row0 + ty * 4 + i) * DD + tx * 8;
            float4 o0 = {acc[i][0], acc[i][1], acc[i][2], acc[i][3]};
            float4 o1 = {acc[i][4], acc[i][5], acc[i][6], acc[i][7]};
            *(float4*)&out[base] = o0; *(float4*)&out[base + 4] = o1;
        }
    }
}

// ---------------- kernel 2: pool -> K,V hi/lo ----------------
__global__ void pool_kernel()
{
    int i = blockIdx.x * blockDim.x + threadIdx.x;
    if (i >= BSZ * NN * DD) return;
    int m = (i / DD) % NN;
    float kv = 0.f, vv = 0.f;
    if (m < MM) {
        kv = fmaxf(g_phi[i], g_phi[i + DD]);
        vv = fmaxf(g_gv[i],  g_gv[i + DD]);
    }
    __nv_bfloat16 kh = bhi(kv), vh = bhi(vv);
    g_kh[i] = kh; g_kl[i] = blo(kv, kh);
    g_vh[i] = vh; g_vl[i] = blo(vv, vh);
}

// ---------------- kernel 3: flash attention (mma.sync bf16x3) ----------------
// smem: padded rows of 136 bf16 (272 B) for conflict-free ldmatrix
#define RSTR   272
#define QH_OFF 0
#define QL_OFF 34816
#define KH_OFF 69632
#define KL_OFF 87040
#define VH_OFF 104448
#define VL_OFF 121856
#define ATT_SMEM 139264

__global__ void __launch_bounds__(256, 1) attn_kernel()
{
    extern __shared__ __align__(16) char sm[];
    const uint32_t sb = s2u(sm);
    const int tid = threadIdx.x, w = tid >> 5, lane = tid & 31;
    const int b = blockIdx.y, q0 = blockIdx.x * 128;
    const int g = lane >> 2, t = lane & 3;

    // load Q hi/lo into smem (once)
    {
        const uint4* qh = (const uint4*)(g_th + ((size_t)b * NN + q0) * DD);
        const uint4* ql = (const uint4*)(g_tl + ((size_t)b * NN + q0) * DD);
#pragma unroll
        for (int i = 0; i < 8; i++) {
            int f = tid + i * 256;
            uint32_t off = (uint32_t)(f >> 4) * RSTR + (uint32_t)(f & 15) * 16;
            *(uint4*)(sm + QH_OFF + off) = qh[f];
            *(uint4*)(sm + QL_OFF + off) = ql[f];
        }
    }

    float O[16][4];
#pragma unroll
    for (int i = 0; i < 16; i++)
#pragma unroll
        for (int j = 0; j < 4; j++) O[i][j] = 0.f;
    float mA = -1e30f, mB = -1e30f, lA = 0.f, lB = 0.f;

    const uint4* kh4 = (const uint4*)(g_kh + (size_t)b * NN * DD);
    const uint4* kl4 = (const uint4*)(g_kl + (size_t)b * NN * DD);
    const uint4* vh4 = (const uint4*)(g_vh + (size_t)b * NN * DD);
    const uint4* vl4 = (const uint4*)(g_vl + (size_t)b * NN * DD);

    const uint32_t qaddr0 = sb + QH_OFF + (uint32_t)(w * 16 + (lane & 15)) * RSTR
                          + (uint32_t)(lane >> 4) * 16;
    const uint32_t kaddr0 = sb + KH_OFF + (uint32_t)(lane & 7) * RSTR
                          + (uint32_t)((lane >> 3) & 1) * 16;
    const uint32_t vaddr0 = sb + VH_OFF + (uint32_t)(lane & 15) * RSTR
                          + (uint32_t)(lane >> 4) * 16;

    for (int kt = 0; kt < NKT; kt++) {
        __syncthreads();
        // load K,V tile (64 x 128, hi+lo)
#pragma unroll
        for (int i = 0; i < 4; i++) {
            int f = tid + i * 256;
            uint32_t off = (uint32_t)(f >> 4) * RSTR + (uint32_t)(f & 15) * 16;
            size_t gi = (size_t)kt * 1024 + f;
            *(uint4*)(sm + KH_OFF + off) = kh4[gi];
            *(uint4*)(sm + KL_OFF + off) = kl4[gi];
            *(uint4*)(sm + VH_OFF + off) = vh4[gi];
            *(uint4*)(sm + VL_OFF + off) = vl4[gi];
        }
        __syncthreads();

        // ---- S = Q K^T (bf16x3) ----
        float S[8][4];
#pragma unroll
        for (int i = 0; i < 8; i++)
#pragma unroll
            for (int j = 0; j < 4; j++) S[i][j] = 0.f;

#pragma unroll
        for (int kc = 0; kc < 8; kc++) {
            uint32_t Ah[4], Al[4];
            uint32_t qa = qaddr0 + kc * 32;
            ldsm_x4(Ah, qa);
            ldsm_x4(Al, qa + (QL_OFF - QH_OFF));
#pragma unroll
            for (int nt = 0; nt < 8; nt++) {
                uint32_t Bh[2], Bl[2];
                uint32_t ka = kaddr0 + (uint32_t)nt * 8 * RSTR + kc * 32;
                ldsm_x2(Bh, ka);
                ldsm_x2(Bl, ka + (KL_OFF - KH_OFF));
                mma16816(S[nt], Ah, Bh);
                mma16816(S[nt], Al, Bh);
                mma16816(S[nt], Ah, Bl);
            }
        }

        // mask key m=4095 (last col of last tile)
        if (kt == NKT - 1 && t == 3) { S[7][1] = -1e30f; S[7][3] = -1e30f; }

        // ---- online softmax ----
        float mlA = -1e30f, mlB = -1e30f;
#pragma unroll
        for (int nt = 0; nt < 8; nt++) {
            mlA = fmaxf(mlA, fmaxf(S[nt][0], S[nt][1]));
            mlB = fmaxf(mlB, fmaxf(S[nt][2], S[nt][3]));
        }
        mlA = fmaxf(mlA, __shfl_xor_sync(0xffffffffu, mlA, 1));
        mlA = fmaxf(mlA, __shfl_xor_sync(0xffffffffu, mlA, 2));
        mlB = fmaxf(mlB, __shfl_xor_sync(0xffffffffu, mlB, 1));
        mlB = fmaxf(mlB, __shfl_xor_sync(0xffffffffu, mlB, 2));

        float mnA = fmaxf(mA, mlA), mnB = fmaxf(mB, mlB);
        float scA = __expf(mA - mnA), scB = __expf(mB - mnB);
        mA = mnA; mB = mnB;

        float lsA = 0.f, lsB = 0.f;
#pragma unroll
        for (int nt = 0; nt < 8; nt++) {
            S[nt][0] = __expf(S[nt][0] - mnA);
            S[nt][1] = __expf(S[nt][1] - mnA);
            S[nt][2] = __expf(S[nt][2] - mnB);
            S[nt][3] = __expf(S[nt][3] - mnB);
            lsA += S[nt][0] + S[nt][1];
            lsB += S[nt][2] + S[nt][3];
        }
        lsA += __shfl_xor_sync(0xffffffffu, lsA, 1);
        lsA += __shfl_xor_sync(0xffffffffu, lsA, 2);
        lsB += __shfl_xor_sync(0xffffffffu, lsB, 1);
        lsB += __shfl_xor_sync(0xffffffffu, lsB, 2);
        lA = lA * scA + lsA;
        lB = lB * scB + lsB;

#pragma unroll
        for (int i = 0; i < 16; i++) {
            O[i][0] *= scA; O[i][1] *= scA;
            O[i][2] *= scB; O[i][3] *= scB;
        }

        // ---- O += P V (bf16x3), P built from S fragments in regs ----
#pragma unroll
        for (int kk = 0; kk < 4; kk++) {
            uint32_t Ph[4], Pl[4];
            {
                const float* s0 = S[2 * kk];
                const float* s1 = S[2 * kk + 1];
                float h[8], lo[8];
#pragma unroll
                for (int e = 0; e < 4; e++) {
                    float p0 = s0[e], p1 = s1[e];
                    float h0 = __uint_as_float(__float_as_uint(p0) & 0xffff0000u);
                    float h1 = __uint_as_float(__float_as_uint(p1) & 0xffff0000u);
                    h[e] = h0; lo[e] = p0 - h0;
                    h[4 + e] = h1; lo[4 + e] = p1 - h1;
                }
                Ph[0] = packbf(h[0], h[1]);  Ph[1] = packbf(h[2], h[3]);
                Ph[2] = packbf(h[4], h[5]);  Ph[3] = packbf(h[6], h[7]);
                Pl[0] = packbf(lo[0], lo[1]); Pl[1] = packbf(lo[2], lo[3]);
                Pl[2] = packbf(lo[4], lo[5]); Pl[3] = packbf(lo[6], lo[7]);
            }
#pragma unroll
            for (int nd = 0; nd < 8; nd++) {
                uint32_t Vh[4], Vl[4];
                uint32_t va = vaddr0 + (uint32_t)kk * 16 * RSTR + (uint32_t)nd * 32;
                ldsm_x4t(Vh, va);
                ldsm_x4t(Vl, va + (VL_OFF - VH_OFF));
                mma16816(O[2 * nd],     Ph, &Vh[0]);
                mma16816(O[2 * nd],     Pl, &Vh[0]);
                mma16816(O[2 * nd],     Ph, &Vl[0]);
                mma16816(O[2 * nd + 1], Ph, &Vh[2]);
                mma16816(O[2 * nd + 1], Pl, &Vh[2]);
                mma16816(O[2 * nd + 1], Ph, &Vl[2]);
            }
        }
    }

    // epilogue
    float invA = 1.f / lA, invB = 1.f / lB;
    float* yA = g_y + ((size_t)b * NN + q0 + w * 16 + g) * DD;
    float* yB = yA + 8 * DD;
#pragma unroll
    for (int nd = 0; nd < 16; nd++) {
        int c = nd * 8 + t * 2;
        float2 oa = {O[nd][0] * invA, O[nd][1] * invA};
        float2 ob = {O[nd][2] * invB, O[nd][3] * invB};
        *(float2*)(yA + c) = oa;
        *(float2*)(yB + c) = ob;
    }
}

// ---------------- kernel 4: z = x + y @ Wf ----------------
__global__ void out_kernel(const float* __restrict__ x,
                           const float* __restrict__ Wf,
                           float* __restrict__ z)
{
    __shared__ __align__(16) float Ys[64][DD];
    const int tid = threadIdx.x, ty = tid >> 4, tx = tid & 15;
    const int row0 = blockIdx.x * 64, c0 = blockIdx.y * 64;
    {
        const float4* src = (const float4*)(g_y + (size_t)row0 * DD);
        float4* dst = (float4*)&Ys[0][0];
#pragma unroll
        for (int p = 0; p < 8; p++) dst[tid + p * 256] = src[tid + p * 256];
    }
    __syncthreads();
    float acc[4][4];
#pragma unroll
    for (int i = 0; i < 4; i++)
#pragma unroll
        for (int j = 0; j < 4; j++) acc[i][j] = 0.f;
    const float4* Wf4 = (const float4*)Wf;
#pragma unroll 4
    for (int k = 0; k < DD; k++) {
        float a[4];
#pragma unroll
        for (int i = 0; i < 4; i++) a[i] = Ys[ty * 4 + i][k];
        float4 wv = __ldg(&Wf4[(size_t)k * (CC / 4) + (c0 >> 2) + tx]);
#pragma unroll
        for (int i = 0; i < 4; i++) {
            acc[i][0] = fmaf(a[i], wv.x, acc[i][0]);
            acc[i][1] = fmaf(a[i], wv.y, acc[i][1]);
            acc[i][2] = fmaf(a[i], wv.z, acc[i][2]);
            acc[i][3] = fmaf(a[i], wv.w, acc[i][3]);
        }
    }
#pragma unroll
    for (int i = 0; i < 4; i++) {
        size_t base = (size_t)(row0 + ty * 4 + i) * CC + c0 + tx * 4;
        float4 xv = *(const float4*)&x[base];
        float4 o = {xv.x + acc[i][0], xv.y + acc[i][1], xv.z + acc[i][2], xv.w + acc[i][3]};
        *(float4*)&z[base] = o;
    }
}

// ---------------- launch ----------------
extern "C" void kernel_launch(void* const* d_in, const int* in_sizes, int n_in,
                              void* d_out, int out_size)
{
    const float* x  = (const float*)d_in[0];
    const float* Wt = (const float*)d_in[1];
    const float* Wp = (const float*)d_in[2];
    const float* Wg = (const float*)d_in[3];
    const float* Wf = (const float*)d_in[4];
    float* z = (float*)d_out;

    cudaFuncSetAttribute(attn_kernel, cudaFuncAttributeMaxDynamicSharedMemorySize, ATT_SMEM);

    proj_kernel<<<dim3(BSZ * NN / 64, 3), 256>>>(x, Wt, Wp, Wg);
    pool_kernel<<<(BSZ * NN * DD) / 256, 256>>>();
    attn_kernel<<<dim3(NN / 128, BSZ), 256, ATT_SMEM>>>();
    out_kernel<<<dim3(BSZ * NN / 64, CC / 64), 256>>>(x, Wf, z);
}

// round 7
// speedup vs baseline: 8.2867x; 1.3331x over previous
#include <cuda_runtime.h>
#include <cuda_bf16.h>
#include <cstdint>

#define BSZ 4
#define CC  256
#define DD  128
#define NN  4096
#define MM  4095
#define NKT 64              // key tiles of 64

// ---------------- scratch ----------------
__device__ __align__(16) __nv_bfloat16 g_xh[BSZ*NN*CC];
__device__ __align__(16) __nv_bfloat16 g_xl[BSZ*NN*CC];
__device__ __align__(16) __nv_bfloat16 g_Wh[3*CC*DD];
__device__ __align__(16) __nv_bfloat16 g_Wl[3*CC*DD];
__device__ __align__(16) __nv_bfloat16 g_th[BSZ*NN*DD];
__device__ __align__(16) __nv_bfloat16 g_tl[BSZ*NN*DD];
__device__ __align__(16) float g_phi[BSZ*NN*DD];
__device__ __align__(16) float g_gv [BSZ*NN*DD];
__device__ __align__(16) __nv_bfloat16 g_kh[BSZ*NN*DD];
__device__ __align__(16) __nv_bfloat16 g_kl[BSZ*NN*DD];
__device__ __align__(16) __nv_bfloat16 g_vh[BSZ*NN*DD];
__device__ __align__(16) __nv_bfloat16 g_vl[BSZ*NN*DD];
__device__ __align__(16) float g_y[BSZ*NN*DD];

// ---------------- helpers ----------------
__device__ __forceinline__ uint32_t s2u(const void* p){
    uint32_t a;
    asm("{ .reg .u64 t; cvta.to.shared.u64 t, %1; cvt.u32.u64 %0, t; }" : "=r"(a) : "l"(p));
    return a;
}
__device__ __forceinline__ void ldsm_x4(uint32_t* r, uint32_t a){
    asm volatile("ldmatrix.sync.aligned.m8n8.x4.shared.b16 {%0,%1,%2,%3}, [%4];"
        : "=r"(r[0]),"=r"(r[1]),"=r"(r[2]),"=r"(r[3]) : "r"(a));
}
__device__ __forceinline__ void ldsm_x2(uint32_t* r, uint32_t a){
    asm volatile("ldmatrix.sync.aligned.m8n8.x2.shared.b16 {%0,%1}, [%2];"
        : "=r"(r[0]),"=r"(r[1]) : "r"(a));
}
__device__ __forceinline__ void ldsm_x4t(uint32_t* r, uint32_t a){
    asm volatile("ldmatrix.sync.aligned.m8n8.x4.trans.shared.b16 {%0,%1,%2,%3}, [%4];"
        : "=r"(r[0]),"=r"(r[1]),"=r"(r[2]),"=r"(r[3]) : "r"(a));
}
__device__ __forceinline__ void mma16816(float* c, const uint32_t* a, const uint32_t* b){
    asm volatile("mma.sync.aligned.m16n8k16.row.col.f32.bf16.bf16.f32 "
        "{%0,%1,%2,%3}, {%4,%5,%6,%7}, {%8,%9}, {%0,%1,%2,%3};"
        : "+f"(c[0]),"+f"(c[1]),"+f"(c[2]),"+f"(c[3])
        : "r"(a[0]),"r"(a[1]),"r"(a[2]),"r"(a[3]),"r"(b[0]),"r"(b[1]));
}
__device__ __forceinline__ uint32_t packbf(float lo, float hi){
    uint32_t r; asm("cvt.rn.bf16x2.f32 %0, %1, %2;" : "=r"(r) : "f"(hi), "f"(lo)); return r;
}
__device__ __forceinline__ void cpa16(uint32_t s, const void* g){
    asm volatile("cp.async.cg.shared.global [%0], [%1], 16;" :: "r"(s), "l"(g));
}
#define CPA_COMMIT() asm volatile("cp.async.commit_group;" ::: "memory")
__device__ __forceinline__ __nv_bfloat16 bhi(float v){ return __float2bfloat16(v); }
__device__ __forceinline__ __nv_bfloat16 blo(float v, __nv_bfloat16 h){
    return __float2bfloat16(v - __bfloat162float(h));
}

// ---------------- kernel 0: split x and W into bf16 hi/lo ----------------
__global__ void conv_kernel(const float* __restrict__ x,
                            const float* __restrict__ Wt,
                            const float* __restrict__ Wp,
                            const float* __restrict__ Wg)
{
    int i = blockIdx.x * blockDim.x + threadIdx.x;   // float4 index
    if (i < BSZ * NN * CC / 4) {
        float4 v = ((const float4*)x)[i];
        __nv_bfloat16 h0 = bhi(v.x), h1 = bhi(v.y), h2 = bhi(v.z), h3 = bhi(v.w);
        __nv_bfloat162 H01; H01.x = h0; H01.y = h1;
        __nv_bfloat162 H23; H23.x = h2; H23.y = h3;
        __nv_bfloat162 L01; L01.x = blo(v.x, h0); L01.y = blo(v.y, h1);
        __nv_bfloat162 L23; L23.x = blo(v.z, h2); L23.y = blo(v.w, h3);
        *(__nv_bfloat162*)(g_xh + 4 * i)     = H01;
        *(__nv_bfloat162*)(g_xh + 4 * i + 2) = H23;
        *(__nv_bfloat162*)(g_xl + 4 * i)     = L01;
        *(__nv_bfloat162*)(g_xl + 4 * i + 2) = L23;
    }
    if (i < 3 * CC * DD / 4) {
        int wsel = (4 * i) / (CC * DD), r4 = i % (CC * DD / 4);
        const float* Wm = (wsel == 0) ? Wt : (wsel == 1) ? Wp : Wg;
        float4 v = ((const float4*)Wm)[r4];
        __nv_bfloat16 h0 = bhi(v.x), h1 = bhi(v.y), h2 = bhi(v.z), h3 = bhi(v.w);
        __nv_bfloat162 H01; H01.x = h0; H01.y = h1;
        __nv_bfloat162 H23; H23.x = h2; H23.y = h3;
        __nv_bfloat162 L01; L01.x = blo(v.x, h0); L01.y = blo(v.y, h1);
        __nv_bfloat162 L23; L23.x = blo(v.z, h2); L23.y = blo(v.w, h3);
        *(__nv_bfloat162*)(g_Wh + 4 * i)     = H01;
        *(__nv_bfloat162*)(g_Wh + 4 * i + 2) = H23;
        *(__nv_bfloat162*)(g_Wl + 4 * i)     = L01;
        *(__nv_bfloat162*)(g_Wl + 4 * i + 2) = L23;
    }
}

// ---------------- kernel 1: projections via mma.sync bf16x3 ----------------
// CTA: 128 rows x 128 cols, one weight (blockIdx.y). k chunks of 64.
#define PX_STR 144          // 64 bf16 row + 16B pad
#define PW_STR 272          // 128 bf16 row + 16B pad
#define P_XH 0
#define P_XL 18432
#define P_WH 36864
#define P_WL 54272
#define PROJ_SMEM 71680

__global__ void __launch_bounds__(256, 2) proj_kernel()
{
    extern __shared__ __align__(16) char sm[];
    const uint32_t sb = s2u(sm);
    const int tid = threadIdx.x, w = tid >> 5, lane = tid & 31;
    const int n0 = blockIdx.x * 128, wsel = blockIdx.y;
    const int g = lane >> 2, t = lane & 3;

    const uint4* xh4 = (const uint4*)g_xh;
    const uint4* xl4 = (const uint4*)g_xl;
    const uint4* wh4 = (const uint4*)(g_Wh + wsel * CC * DD);
    const uint4* wl4 = (const uint4*)(g_Wl + wsel * CC * DD);

    float O[16][4];
#pragma unroll
    for (int i = 0; i < 16; i++)
#pragma unroll
        for (int j = 0; j < 4; j++) O[i][j] = 0.f;

    const uint32_t xaddr0 = sb + P_XH + (uint32_t)(w * 16 + (lane & 15)) * PX_STR
                          + (uint32_t)(lane >> 4) * 16;
    const uint32_t waddr0 = sb + P_WH + (uint32_t)(lane & 15) * PW_STR
                          + (uint32_t)(lane >> 4) * 16;

    for (int ch = 0; ch < 4; ch++) {
        __syncthreads();
        // X tile 128x64 (hi/lo): 1024 uint4 each, 4/thread
#pragma unroll
        for (int i = 0; i < 4; i++) {
            int f = tid + i * 256, r = f >> 3, c = f & 7;
            uint32_t off = (uint32_t)r * PX_STR + (uint32_t)c * 16;
            size_t src = (size_t)(n0 + r) * 32 + ch * 8 + c;
            *(uint4*)(sm + P_XH + off) = xh4[src];
            *(uint4*)(sm + P_XL + off) = xl4[src];
        }
        // W tile 64x128 (hi/lo): 1024 uint4 each, 4/thread
#pragma unroll
        for (int i = 0; i < 4; i++) {
            int f = tid + i * 256, r = f >> 4, c = f & 15;
            uint32_t off = (uint32_t)r * PW_STR + (uint32_t)c * 16;
            size_t src = (size_t)(ch * 64 + r) * 16 + c;
            *(uint4*)(sm + P_WH + off) = wh4[src];
            *(uint4*)(sm + P_WL + off) = wl4[src];
        }
        __syncthreads();

#pragma unroll
        for (int kc = 0; kc < 4; kc++) {
            uint32_t Ah[4], Al[4];
            uint32_t xa = xaddr0 + kc * 32;
            ldsm_x4(Ah, xa);
            ldsm_x4(Al, xa + (P_XL - P_XH));
#pragma unroll
            for (int nd = 0; nd < 8; nd++) {
                uint32_t Bh[4], Bl[4];
                uint32_t wa = waddr0 + (uint32_t)kc * 16 * PW_STR + (uint32_t)nd * 32;
                ldsm_x4t(Bh, wa);
                ldsm_x4t(Bl, wa + (P_WL - P_WH));
                mma16816(O[2 * nd],     Ah, &Bh[0]);
                mma16816(O[2 * nd],     Al, &Bh[0]);
                mma16816(O[2 * nd],     Ah, &Bl[0]);
                mma16816(O[2 * nd + 1], Ah, &Bh[2]);
                mma16816(O[2 * nd + 1], Al, &Bh[2]);
                mma16816(O[2 * nd + 1], Ah, &Bl[2]);
            }
        }
    }

    // store
    int r0 = n0 + w * 16 + g;
    if (wsel == 0) {
#pragma unroll
        for (int nt = 0; nt < 16; nt++) {
            int c = nt * 8 + t * 2;
            float v0 = O[nt][0], v1 = O[nt][1], v2 = O[nt][2], v3 = O[nt][3];
            __nv_bfloat16 h0 = bhi(v0), h1 = bhi(v1), h2 = bhi(v2), h3 = bhi(v3);
            __nv_bfloat162 H0; H0.x = h0; H0.y = h1;
            __nv_bfloat162 L0; L0.x = blo(v0, h0); L0.y = blo(v1, h1);
            __nv_bfloat162 H1; H1.x = h2; H1.y = h3;
            __nv_bfloat162 L1; L1.x = blo(v2, h2); L1.y = blo(v3, h3);
            *(__nv_bfloat162*)(g_th + (size_t)r0 * DD + c)       = H0;
            *(__nv_bfloat162*)(g_tl + (size_t)r0 * DD + c)       = L0;
            *(__nv_bfloat162*)(g_th + (size_t)(r0 + 8) * DD + c) = H1;
            *(__nv_bfloat162*)(g_tl + (size_t)(r0 + 8) * DD + c) = L1;
        }
    } else {
        float* out = (wsel == 1) ? g_phi : g_gv;
#pragma unroll
        for (int nt = 0; nt < 16; nt++) {
            int c = nt * 8 + t * 2;
            float2 a = {O[nt][0], O[nt][1]};
            float2 b = {O[nt][2], O[nt][3]};
            *(float2*)(out + (size_t)r0 * DD + c)       = a;
            *(float2*)(out + (size_t)(r0 + 8) * DD + c) = b;
        }
    }
}

// ---------------- kernel 2: pool -> K,V hi/lo ----------------
__global__ void pool_kernel()
{
    int i = blockIdx.x * blockDim.x + threadIdx.x;
    if (i >= BSZ * NN * DD) return;
    int m = (i / DD) % NN;
    float kv = 0.f, vv = 0.f;
    if (m < MM) {
        kv = fmaxf(g_phi[i], g_phi[i + DD]);
        vv = fmaxf(g_gv[i],  g_gv[i + DD]);
    }
    __nv_bfloat16 kh = bhi(kv), vh = bhi(vv);
    g_kh[i] = kh; g_kl[i] = blo(kv, kh);
    g_vh[i] = vh; g_vl[i] = blo(vv, vh);
}

// ---------------- kernel 3: flash attention (mma.sync bf16x3, cp.async 2-stage) --
#define RSTR   272
#define QH_OFF 0
#define QL_OFF 34816
#define KV_OFF 69632
#define STG    69632          // per-stage bytes
#define SKH    0
#define SKL    17408
#define SVH    34816
#define SVL    52224
#define ATT_SMEM (69632 * 3)  // 208896

__global__ void __launch_bounds__(256, 1) attn_kernel()
{
    extern __shared__ __align__(16) char sm[];
    const uint32_t sb = s2u(sm);
    const int tid = threadIdx.x, w = tid >> 5, lane = tid & 31;
    const int b = blockIdx.y, q0 = blockIdx.x * 128;
    const int g = lane >> 2, t = lane & 3;

    // load Q hi/lo into smem (once)
    {
        const uint4* qh = (const uint4*)(g_th + ((size_t)b * NN + q0) * DD);
        const uint4* ql = (const uint4*)(g_tl + ((size_t)b * NN + q0) * DD);
#pragma unroll
        for (int i = 0; i < 8; i++) {
            int f = tid + i * 256;
            uint32_t off = (uint32_t)(f >> 4) * RSTR + (uint32_t)(f & 15) * 16;
            *(uint4*)(sm + QH_OFF + off) = qh[f];
            *(uint4*)(sm + QL_OFF + off) = ql[f];
        }
    }

    float O[16][4];
#pragma unroll
    for (int i = 0; i < 16; i++)
#pragma unroll
        for (int j = 0; j < 4; j++) O[i][j] = 0.f;
    float mA = -1e30f, mB = -1e30f, lA = 0.f, lB = 0.f;

    const uint4* kh4 = (const uint4*)(g_kh + (size_t)b * NN * DD);
    const uint4* kl4 = (const uint4*)(g_kl + (size_t)b * NN * DD);
    const uint4* vh4 = (const uint4*)(g_vh + (size_t)b * NN * DD);
    const uint4* vl4 = (const uint4*)(g_vl + (size_t)b * NN * DD);

    const uint32_t qaddr0 = sb + QH_OFF + (uint32_t)(w * 16 + (lane & 15)) * RSTR
                          + (uint32_t)(lane >> 4) * 16;

    // per-thread cp.async offsets (4 chunks of 256 threads)
    uint32_t soff[4]; size_t goff[4];
#pragma unroll
    for (int i = 0; i < 4; i++) {
        int f = tid + i * 256;
        soff[i] = (uint32_t)(f >> 4) * RSTR + (uint32_t)(f & 15) * 16;
        goff[i] = f;
    }

    // prologue: issue tile 0 into stage 0
    {
        uint32_t base = sb + KV_OFF;
#pragma unroll
        for (int i = 0; i < 4; i++) {
            cpa16(base + SKH + soff[i], kh4 + goff[i]);
            cpa16(base + SKL + soff[i], kl4 + goff[i]);
            cpa16(base + SVH + soff[i], vh4 + goff[i]);
            cpa16(base + SVL + soff[i], vl4 + goff[i]);
        }
        CPA_COMMIT();
    }

    for (int kt = 0; kt < NKT; kt++) {
        const int cur = kt & 1;
        if (kt + 1 < NKT) {
            uint32_t base = sb + KV_OFF + (uint32_t)(cur ^ 1) * STG;
            size_t gi = (size_t)(kt + 1) * 1024;
#pragma unroll
            for (int i = 0; i < 4; i++) {
                cpa16(base + SKH + soff[i], kh4 + gi + goff[i]);
                cpa16(base + SKL + soff[i], kl4 + gi + goff[i]);
                cpa16(base + SVH + soff[i], vh4 + gi + goff[i]);
                cpa16(base + SVL + soff[i], vl4 + gi + goff[i]);
            }
            CPA_COMMIT();
            asm volatile("cp.async.wait_group 1;" ::: "memory");
        } else {
            asm volatile("cp.async.wait_group 0;" ::: "memory");
        }
        __syncthreads();

        const uint32_t kaddr0 = sb + KV_OFF + (uint32_t)cur * STG + SKH
                              + (uint32_t)(lane & 7) * RSTR + (uint32_t)((lane >> 3) & 1) * 16;
        const uint32_t vaddr0 = sb + KV_OFF + (uint32_t)cur * STG + SVH
                              + (uint32_t)(lane & 15) * RSTR + (uint32_t)(lane >> 4) * 16;

        // ---- S = Q K^T (bf16x3) ----
        float S[8][4];
#pragma unroll
        for (int i = 0; i < 8; i++)
#pragma unroll
            for (int j = 0; j < 4; j++) S[i][j] = 0.f;

#pragma unroll
        for (int kc = 0; kc < 8; kc++) {
            uint32_t Ah[4], Al[4];
            uint32_t qa = qaddr0 + kc * 32;
            ldsm_x4(Ah, qa);
            ldsm_x4(Al, qa + (QL_OFF - QH_OFF));
#pragma unroll
            for (int nt = 0; nt < 8; nt++) {
                uint32_t Bh[2], Bl[2];
                uint32_t ka = kaddr0 + (uint32_t)nt * 8 * RSTR + kc * 32;
                ldsm_x2(Bh, ka);
                ldsm_x2(Bl, ka + (SKL - SKH));
                mma16816(S[nt], Ah, Bh);
                mma16816(S[nt], Al, Bh);
                mma16816(S[nt], Ah, Bl);
            }
        }

        // mask key m=4095 (last col of last tile)
        if (kt == NKT - 1 && t == 3) { S[7][1] = -1e30f; S[7][3] = -1e30f; }

        // ---- online softmax ----
        float mlA = -1e30f, mlB = -1e30f;
#pragma unroll
        for (int nt = 0; nt < 8; nt++) {
            mlA = fmaxf(mlA, fmaxf(S[nt][0], S[nt][1]));
            mlB = fmaxf(mlB, fmaxf(S[nt][2], S[nt][3]));
        }
        mlA = fmaxf(mlA, __shfl_xor_sync(0xffffffffu, mlA, 1));
        mlA = fmaxf(mlA, __shfl_xor_sync(0xffffffffu, mlA, 2));
        mlB = fmaxf(mlB, __shfl_xor_sync(0xffffffffu, mlB, 1));
        mlB = fmaxf(mlB, __shfl_xor_sync(0xffffffffu, mlB, 2));

        float mnA = fmaxf(mA, mlA), mnB = fmaxf(mB, mlB);
        float scA = __expf(mA - mnA), scB = __expf(mB - mnB);
        mA = mnA; mB = mnB;

        float lsA = 0.f, lsB = 0.f;
#pragma unroll
        for (int nt = 0; nt < 8; nt++) {
            S[nt][0] = __expf(S[nt][0] - mnA);
            S[nt][1] = __expf(S[nt][1] - mnA);
            S[nt][2] = __expf(S[nt][2] - mnB);
            S[nt][3] = __expf(S[nt][3] - mnB);
            lsA += S[nt][0] + S[nt][1];
            lsB += S[nt][2] + S[nt][3];
        }
        lsA += __shfl_xor_sync(0xffffffffu, lsA, 1);
        lsA += __shfl_xor_sync(0xffffffffu, lsA, 2);
        lsB += __shfl_xor_sync(0xffffffffu, lsB, 1);
        lsB += __shfl_xor_sync(0xffffffffu, lsB, 2);
        lA = lA * scA + lsA;
        lB = lB * scB + lsB;

#pragma unroll
        for (int i = 0; i < 16; i++) {
            O[i][0] *= scA; O[i][1] *= scA;
            O[i][2] *= scB; O[i][3] *= scB;
        }

        // ---- O += P V (bf16x3), P from S fragments in regs ----
#pragma unroll
        for (int kk = 0; kk < 4; kk++) {
            uint32_t Ph[4], Pl[4];
            {
                const float* s0 = S[2 * kk];
                const float* s1 = S[2 * kk + 1];
                float h[8], lo[8];
#pragma unroll
                for (int e = 0; e < 4; e++) {
                    float p0 = s0[e], p1 = s1[e];
                    float h0 = __uint_as_float(__float_as_uint(p0) & 0xffff0000u);
                    float h1 = __uint_as_float(__float_as_uint(p1) & 0xffff0000u);
                    h[e] = h0; lo[e] = p0 - h0;
                    h[4 + e] = h1; lo[4 + e] = p1 - h1;
                }
                Ph[0] = packbf(h[0], h[1]);  Ph[1] = packbf(h[2], h[3]);
                Ph[2] = packbf(h[4], h[5]);  Ph[3] = packbf(h[6], h[7]);
                Pl[0] = packbf(lo[0], lo[1]); Pl[1] = packbf(lo[2], lo[3]);
                Pl[2] = packbf(lo[4], lo[5]); Pl[3] = packbf(lo[6], lo[7]);
            }
#pragma unroll
            for (int nd = 0; nd < 8; nd++) {
                uint32_t Vh[4], Vl[4];
                uint32_t va = vaddr0 + (uint32_t)kk * 16 * RSTR + (uint32_t)nd * 32;
                ldsm_x4t(Vh, va);
                ldsm_x4t(Vl, va + (SVL - SVH));
                mma16816(O[2 * nd],     Ph, &Vh[0]);
                mma16816(O[2 * nd],     Pl, &Vh[0]);
                mma16816(O[2 * nd],     Ph, &Vl[0]);
                mma16816(O[2 * nd + 1], Ph, &Vh[2]);
                mma16816(O[2 * nd + 1], Pl, &Vh[2]);
                mma16816(O[2 * nd + 1], Ph, &Vl[2]);
            }
        }
        __syncthreads();
    }

    // epilogue
    float invA = 1.f / lA, invB = 1.f / lB;
    float* yA = g_y + ((size_t)b * NN + q0 + w * 16 + g) * DD;
    float* yB = yA + 8 * DD;
#pragma unroll
    for (int nd = 0; nd < 16; nd++) {
        int c = nd * 8 + t * 2;
        float2 oa = {O[nd][0] * invA, O[nd][1] * invA};
        float2 ob = {O[nd][2] * invB, O[nd][3] * invB};
        *(float2*)(yA + c) = oa;
        *(float2*)(yB + c) = ob;
    }
}

// ---------------- kernel 4: z = x + y @ Wf (smem Wf, 8x4 micro) ----------------
#define OY_STR 132
#define OW_STR 68
#define OUT_SMEM (128 * OY_STR * 4 + 128 * OW_STR * 4)   // 102400

__global__ void __launch_bounds__(256, 2) out_kernel(const float* __restrict__ x,
                                                     const float* __restrict__ Wf,
                                                     float* __restrict__ z)
{
    extern __shared__ __align__(16) float osm[];
    float* Ys  = osm;                   // [128][132]
    float* Wfs = osm + 128 * OY_STR;    // [128][68]

    const int tid = threadIdx.x, ty = tid >> 4, tx = tid & 15;
    const int row0 = blockIdx.x * 128, c0 = blockIdx.y * 64;

    // load Y tile [128,128]: 4096 float4, 16/thread
    {
        const float4* src = (const float4*)(g_y + (size_t)row0 * DD);
#pragma unroll
        for (int p = 0; p < 16; p++) {
            int f = tid + p * 256, r = f >> 5, c = (f & 31) * 4;
            *(float4*)&Ys[r * OY_STR + c] = src[f];
        }
    }
    // load Wf tile [128,64]: 2048 float4, 8/thread
    {
#pragma unroll
        for (int p = 0; p < 8; p++) {
            int f = tid + p * 256, r = f >> 4, c = (f & 15) * 4;
            *(float4*)&Wfs[r * OW_STR + c] = *(const float4*)&Wf[(size_t)r * CC + c0 + c];
        }
    }
    __syncthreads();

    float acc[8][4];
#pragma unroll
    for (int i = 0; i < 8; i++)
#pragma unroll
        for (int j = 0; j < 4; j++) acc[i][j] = 0.f;

#pragma unroll 4
    for (int k = 0; k < DD; k++) {
        float4 wv = *(float4*)&Wfs[k * OW_STR + tx * 4];
        float a[8];
#pragma unroll
        for (int i = 0; i < 8; i++) a[i] = Ys[(ty * 8 + i) * OY_STR + k];
#pragma unroll
        for (int i = 0; i < 8; i++) {
            acc[i][0] = fmaf(a[i], wv.x, acc[i][0]);
            acc[i][1] = fmaf(a[i], wv.y, acc[i][1]);
            acc[i][2] = fmaf(a[i], wv.z, acc[i][2]);
            acc[i][3] = fmaf(a[i], wv.w, acc[i][3]);
        }
    }

#pragma unroll
    for (int i = 0; i < 8; i++) {
        size_t base = (size_t)(row0 + ty * 8 + i) * CC + c0 + tx * 4;
        float4 xv = *(const float4*)&x[base];
        float4 o = {xv.x + acc[i][0], xv.y + acc[i][1], xv.z + acc[i][2], xv.w + acc[i][3]};
        *(float4*)&z[base] = o;
    }
}

// ---------------- launch ----------------
extern "C" void kernel_launch(void* const* d_in, const int* in_sizes, int n_in,
                              void* d_out, int out_size)
{
    const float* x  = (const float*)d_in[0];
    const float* Wt = (const float*)d_in[1];
    const float* Wp = (const float*)d_in[2];
    const float* Wg = (const float*)d_in[3];
    const float* Wf = (const float*)d_in[4];
    float* z = (float*)d_out;

    cudaFuncSetAttribute(proj_kernel, cudaFuncAttributeMaxDynamicSharedMemorySize, PROJ_SMEM);
    cudaFuncSetAttribute(attn_kernel, cudaFuncAttributeMaxDynamicSharedMemorySize, ATT_SMEM);
    cudaFuncSetAttribute(out_kernel,  cudaFuncAttributeMaxDynamicSharedMemorySize, OUT_SMEM);

    conv_kernel<<<(BSZ * NN * CC / 4 + 255) / 256, 256>>>(x, Wt, Wp, Wg);
    proj_kernel<<<dim3(BSZ * NN / 128, 3), 256, PROJ_SMEM>>>();
    pool_kernel<<<(BSZ * NN * DD) / 256, 256>>>();
    attn_kernel<<<dim3(NN / 128, BSZ), 256, ATT_SMEM>>>();
    out_kernel<<<dim3(BSZ * NN / 128, CC / 64), 256, OUT_SMEM>>>(x, Wf, z);
}